// round 3
// baseline (speedup 1.0000x reference)
#include <cuda_runtime.h>
#include <cuda.h>
#include <cuda_bf16.h>
#include <cstdint>
#include <cstdio>

#define BATCH 8192
#define DIMC  2048
#define KDIM  4096

#define MT 128          // CTA rows (batch)
#define NTOT 256        // CTA cols = 4 gates x 64
#define DT 64           // d-columns per gate per CTA
#define KC 16           // k per pipeline stage
#define NK (KDIM / KC)  // 256 iterations
#define NSTAGE 3

// smem (floats): stage = A(128x20) + B(256x20) = 2560 + 5120 = 7680 floats (30720 B)
#define STG_F 7680
#define A_F   2560
// epilogue: 4 gates x 128 x 66 = 33792 floats; bias at 33792..34047
#define EPI_GSTRIDE (128 * 66)
#define BIAS_F (4 * EPI_GSTRIDE)
#define SMEM_F (BIAS_F + 256)
#define SMEM_B (SMEM_F * 4)

__device__ float g_A[(size_t)BATCH * KDIM];
__device__ float g_W[(size_t)4 * DIMC * KDIM];

__device__ __forceinline__ uint32_t smem_u32(const void* p) {
    uint32_t a;
    asm("{ .reg .u64 t; cvta.to.shared.u64 t, %1; cvt.u32.u64 %0, t; }" : "=r"(a) : "l"(p));
    return a;
}
__device__ __forceinline__ void cpa16(uint32_t s, const float* g) {
    asm volatile("cp.async.cg.shared.global [%0], [%1], 16;" :: "r"(s), "l"(g) : "memory");
}
__device__ __forceinline__ float rna_tf32(float x) {
    uint32_t r; asm("cvt.rna.tf32.f32 %0, %1;" : "=r"(r) : "f"(x));
    return __uint_as_float(r);
}
__device__ __forceinline__ void mma_tf32(float* d, const uint32_t* a, const uint32_t* b) {
    asm volatile(
        "mma.sync.aligned.m16n8k8.row.col.f32.tf32.tf32.f32 "
        "{%0,%1,%2,%3}, {%4,%5,%6,%7}, {%8,%9}, {%0,%1,%2,%3};"
        : "+f"(d[0]), "+f"(d[1]), "+f"(d[2]), "+f"(d[3])
        : "r"(a[0]), "r"(a[1]), "r"(a[2]), "r"(a[3]), "r"(b[0]), "r"(b[1]));
}

// ---------------- prep: rna-round + pack operands ----------------
__global__ void prep_A_kernel(const float* __restrict__ x, const float* __restrict__ h) {
    size_t idx = (size_t)blockIdx.x * blockDim.x + threadIdx.x;   // float4 idx
    size_t b = idx >> 10; int k4 = (int)(idx & 1023);
    const float4* src = (k4 < 512) ? (reinterpret_cast<const float4*>(x) + b * 512 + k4)
                                   : (reinterpret_cast<const float4*>(h) + b * 512 + (k4 - 512));
    float4 v = *src;
    v.x = rna_tf32(v.x); v.y = rna_tf32(v.y); v.z = rna_tf32(v.z); v.w = rna_tf32(v.w);
    reinterpret_cast<float4*>(g_A)[idx] = v;
}
__global__ void prep_W_kernel(const float* __restrict__ wi, const float* __restrict__ wf,
                              const float* __restrict__ wo, const float* __restrict__ wz) {
    size_t idx = (size_t)blockIdx.x * blockDim.x + threadIdx.x;
    size_t j = idx >> 10; int k4 = (int)(idx & 1023);
    int g = (int)(j >> 11); size_t r = j & 2047;
    const float* W = (g == 0) ? wi : (g == 1) ? wf : (g == 2) ? wo : wz;
    float4 v = reinterpret_cast<const float4*>(W)[r * 1024 + k4];
    v.x = rna_tf32(v.x); v.y = rna_tf32(v.y); v.z = rna_tf32(v.z); v.w = rna_tf32(v.w);
    reinterpret_cast<float4*>(g_W)[idx] = v;
}

// ---------------- fused GEMM + sLSTM ----------------
__global__ void __launch_bounds__(256, 1)
slstm_gemm(const float* __restrict__ gA, const float* __restrict__ gW,
           const float* __restrict__ c_in, const float* __restrict__ n_in,
           const float* __restrict__ m_in,
           const float* __restrict__ bi, const float* __restrict__ bf_,
           const float* __restrict__ bo, const float* __restrict__ bz,
           float* __restrict__ out)
{
    extern __shared__ float sm[];
    const int tid = threadIdx.x;
    const int lane = tid & 31, wid = tid >> 5;
    const int wm = wid & 1, wn = wid >> 1;     // warp: M-half, gate (N-quarter)

    // supergroup swizzle: 4 groups of (16 m-tiles x 32 d-tiles)
    int bid = blockIdx.x;
    int sg = bid >> 9, r = bid & 511;
    int mt = (sg << 4) + (r & 15), dt = r >> 4;
    const int m0 = mt * MT, d0 = dt * DT;

    // biases -> smem tail
    {
        int g = tid >> 6, j = tid & 63;
        const float* bb = (g == 0) ? bi : (g == 1) ? bf_ : (g == 2) ? bo : bz;
        sm[BIAS_F + tid] = bb[d0 + j];
    }

    const uint32_t smb = smem_u32(sm);

    // per-thread cp.async assignments (chunk = 16B = 4 floats)
    // A: 512 chunks -> 2/thread ; B: 1024 chunks -> 4/thread
    int ac[2], bcN[4];
    uint32_t aSo[2], bSo[4];
    const float* aGp[2];
    const float* bGp[4];
    #pragma unroll
    for (int q = 0; q < 2; ++q) {
        int c = tid + q * 256, mm = c >> 2, kc = c & 3;
        ac[q] = mm;
        aSo[q] = (uint32_t)(mm * 80 + kc * 16);
        aGp[q] = gA + (size_t)(m0 + mm) * KDIM + kc * 4;
    }
    #pragma unroll
    for (int q = 0; q < 4; ++q) {
        int c = tid + q * 256, nn = c >> 2, kc = c & 3;
        int row = ((nn >> 6) << 11) + d0 + (nn & 63);
        bcN[q] = nn;
        bSo[q] = (uint32_t)(A_F * 4 + nn * 80 + kc * 16);
        bGp[q] = gW + (size_t)row * KDIM + kc * 4;
    }
    (void)ac; (void)bcN;

    float acc[4][8][4];
    #pragma unroll
    for (int i = 0; i < 4; ++i)
        #pragma unroll
        for (int j = 0; j < 8; ++j)
            #pragma unroll
            for (int t = 0; t < 4; ++t) acc[i][j][t] = 0.0f;

    // prologue: stages 0,1
    #pragma unroll
    for (int p = 0; p < 2; ++p) {
        uint32_t base = smb + p * (STG_F * 4);
        #pragma unroll
        for (int q = 0; q < 2; ++q) { cpa16(base + aSo[q], aGp[q]); aGp[q] += KC; }
        #pragma unroll
        for (int q = 0; q < 4; ++q) { cpa16(base + bSo[q], bGp[q]); bGp[q] += KC; }
        asm volatile("cp.async.commit_group;" ::: "memory");
    }

    const int aRow0 = wm * 64 + (lane >> 2);
    const int kLane = lane & 3;
    const int bN0 = wn * 64 + (lane >> 2);

    for (int ks = 0; ks < NK; ++ks) {
        if (ks + 2 < NK) asm volatile("cp.async.wait_group 1;" ::: "memory");
        else             asm volatile("cp.async.wait_group 0;" ::: "memory");
        __syncthreads();

        if (ks + 2 < NK) {
            uint32_t base = smb + ((ks + 2) % NSTAGE) * (STG_F * 4);
            #pragma unroll
            for (int q = 0; q < 2; ++q) { cpa16(base + aSo[q], aGp[q]); aGp[q] += KC; }
            #pragma unroll
            for (int q = 0; q < 4; ++q) { cpa16(base + bSo[q], bGp[q]); bGp[q] += KC; }
            asm volatile("cp.async.commit_group;" ::: "memory");
        }

        const float* sA = sm + (ks % NSTAGE) * STG_F;
        const float* sB = sA + A_F;
        #pragma unroll
        for (int kstep = 0; kstep < 2; ++kstep) {
            const int kb = kstep * 8 + kLane;
            uint32_t af[4][4], bf[8][2];
            #pragma unroll
            for (int i = 0; i < 4; ++i) {
                int rr = aRow0 + i * 16;
                af[i][0] = __float_as_uint(sA[rr * 20 + kb]);
                af[i][1] = __float_as_uint(sA[(rr + 8) * 20 + kb]);
                af[i][2] = __float_as_uint(sA[rr * 20 + kb + 4]);
                af[i][3] = __float_as_uint(sA[(rr + 8) * 20 + kb + 4]);
            }
            #pragma unroll
            for (int j = 0; j < 8; ++j) {
                int nn = bN0 + j * 8;
                bf[j][0] = __float_as_uint(sB[nn * 20 + kb]);
                bf[j][1] = __float_as_uint(sB[nn * 20 + kb + 4]);
            }
            #pragma unroll
            for (int i = 0; i < 4; ++i)
                #pragma unroll
                for (int j = 0; j < 8; ++j)
                    mma_tf32(acc[i][j], af[i], bf[j]);
        }
        __syncthreads();
    }

    // ------------- epilogue: accums -> smem (per gate), then fused sLSTM -------------
    {
        float* sg_ = sm + wn * EPI_GSTRIDE;   // warp wn owns gate wn
        #pragma unroll
        for (int i = 0; i < 4; ++i) {
            int rr = wm * 64 + i * 16 + (lane >> 2);
            #pragma unroll
            for (int j = 0; j < 8; ++j) {
                int cc = j * 8 + 2 * (lane & 3);
                *reinterpret_cast<float2*>(&sg_[rr * 66 + cc]) =
                    make_float2(acc[i][j][0], acc[i][j][1]);
                *reinterpret_cast<float2*>(&sg_[(rr + 8) * 66 + cc]) =
                    make_float2(acc[i][j][2], acc[i][j][3]);
            }
        }
    }
    __syncthreads();

    {
        const int dloc = tid & 63, mb = tid >> 6;
        const float bI = sm[BIAS_F + dloc];
        const float bF = sm[BIAS_F + 64 + dloc];
        const float bO = sm[BIAS_F + 128 + dloc];
        const float bZ = sm[BIAS_F + 192 + dloc];
        const size_t PL = (size_t)BATCH * DIMC;
        #pragma unroll 4
        for (int rr = 0; rr < 32; ++rr) {
            int mm = rr * 4 + mb;
            size_t gx = (size_t)(m0 + mm) * DIMC + d0 + dloc;
            float it = sm[0 * EPI_GSTRIDE + mm * 66 + dloc] + bI;
            float ft = sm[1 * EPI_GSTRIDE + mm * 66 + dloc] + bF;
            float ot = sm[2 * EPI_GSTRIDE + mm * 66 + dloc] + bO;
            float zt = sm[3 * EPI_GSTRIDE + mm * 66 + dloc] + bZ;
            float cv = c_in[gx], nv = n_in[gx], mv = m_in[gx];
            float z  = tanhf(zt);
            float mn = fmaxf(ft + mv, it);
            float ei = __expf(it - mn);
            float ef = __expf(ft + mv - mn);
            float cn = ef * cv + ei * z;
            float nn2 = ef * nv + ei;
            float sgm = 1.0f / (1.0f + __expf(-ot));
            float hn = sgm * cn / (nn2 + 1e-6f);
            out[gx]          = hn;
            out[PL + gx]     = cn;
            out[2 * PL + gx] = nn2;
            out[3 * PL + gx] = mn;
        }
    }
}

extern "C" void kernel_launch(void* const* d_in, const int* in_sizes, int n_in_cnt,
                              void* d_out, int out_size)
{
    (void)in_sizes; (void)n_in_cnt; (void)out_size;
    const float* x  = (const float*)d_in[0];
    const float* h  = (const float*)d_in[1];
    const float* c  = (const float*)d_in[2];
    const float* nn = (const float*)d_in[3];
    const float* m  = (const float*)d_in[4];
    const float* Wi = (const float*)d_in[5];
    const float* bi = (const float*)d_in[6];
    const float* Wf = (const float*)d_in[7];
    const float* bf = (const float*)d_in[8];
    const float* Wo = (const float*)d_in[9];
    const float* bo = (const float*)d_in[10];
    const float* Wz = (const float*)d_in[11];
    const float* bz = (const float*)d_in[12];
    float* out = (float*)d_out;

    void* pA = nullptr; void* pW = nullptr;
    cudaGetSymbolAddress(&pA, g_A);
    cudaGetSymbolAddress(&pW, g_W);

    prep_A_kernel<<<(BATCH * (KDIM / 4)) / 256, 256>>>(x, h);
    prep_W_kernel<<<(4 * DIMC * (KDIM / 4)) / 256, 256>>>(Wi, Wf, Wo, Wz);

    static bool attr_done = false;
    if (!attr_done) {
        cudaFuncSetAttribute(slstm_gemm, cudaFuncAttributeMaxDynamicSharedMemorySize, SMEM_B);
        attr_done = true;
    }
    int grid = (BATCH / MT) * (DIMC / DT);   // 64 * 32 = 2048
    slstm_gemm<<<grid, 256, SMEM_B>>>((const float*)pA, (const float*)pW,
                                      c, nn, m, bi, bf, bo, bz, out);
}

// round 4
// speedup vs baseline: 2.2597x; 2.2597x over previous
#include <cuda_runtime.h>
#include <cuda.h>
#include <cuda_fp16.h>
#include <cstdint>
#include <cstdio>

#define BATCH 8192
#define DIMC  2048
#define KDIM  4096

#define MT 128
#define DT 64            // d-cols per gate per CTA; N_total = 256
#define KCH 64           // k (halves) per stage; 128B rows
#define NKI (KDIM / KCH) // 64 iterations
#define STG_B 49152      // A 128*128 + B 256*128 bytes
#define EPI_GS 8448      // floats per gate buffer: 128*66
#define BIAS_FO 36864    // float offset of bias region (= 3*STG_B/4)
#define SMEM_B 148480    // 3*49152 + 1024

__device__ __half g_Ah[(size_t)BATCH * KDIM];
__device__ __half g_Wh[(size_t)4 * DIMC * KDIM];

__device__ __forceinline__ uint32_t smem_u32(const void* p) {
    uint32_t a;
    asm("{ .reg .u64 t; cvta.to.shared.u64 t, %1; cvt.u32.u64 %0, t; }" : "=r"(a) : "l"(p));
    return a;
}
__device__ __forceinline__ void cpa16(uint32_t s, const void* g) {
    asm volatile("cp.async.cg.shared.global [%0], [%1], 16;" :: "r"(s), "l"(g) : "memory");
}
__device__ __forceinline__ void lds64(uint32_t a, uint32_t& x, uint32_t& y) {
    asm volatile("ld.shared.v2.b32 {%0, %1}, [%2];" : "=r"(x), "=r"(y) : "r"(a));
}
__device__ __forceinline__ void mma_f16(float* d, const uint32_t* a, const uint32_t* b) {
    asm volatile(
        "mma.sync.aligned.m16n8k16.row.col.f32.f16.f16.f32 "
        "{%0,%1,%2,%3}, {%4,%5,%6,%7}, {%8,%9}, {%0,%1,%2,%3};"
        : "+f"(d[0]), "+f"(d[1]), "+f"(d[2]), "+f"(d[3])
        : "r"(a[0]), "r"(a[1]), "r"(a[2]), "r"(a[3]), "r"(b[0]), "r"(b[1]));
}
__device__ __forceinline__ uint32_t pack2(float a, float b) {
    __half2 h = __floats2half2_rn(a, b);
    return *reinterpret_cast<uint32_t*>(&h);
}

// ---- prep: f32 -> f16 (RNE) with per-16 k-permutation ----
// stored quad (g, kl) holds orig k = g*16 + {2kl, 2kl+1, 2kl+8, 2kl+9}
__global__ void prep_A_kernel(const float* __restrict__ x, const float* __restrict__ h) {
    size_t o = (size_t)blockIdx.x * blockDim.x + threadIdx.x;   // quad id
    size_t row = o >> 10; int q = (int)(o & 1023);
    int g = q >> 2, kl = q & 3;
    int cb = g * 16 + 2 * kl;
    const float* src = (cb < 2048) ? (x + row * 2048 + cb) : (h + row * 2048 + (cb - 2048));
    float2 v0 = *reinterpret_cast<const float2*>(src);
    float2 v1 = *reinterpret_cast<const float2*>(src + 8);
    reinterpret_cast<uint2*>(g_Ah)[o] = make_uint2(pack2(v0.x, v0.y), pack2(v1.x, v1.y));
}
__global__ void prep_W_kernel(const float* __restrict__ wi, const float* __restrict__ wf,
                              const float* __restrict__ wo, const float* __restrict__ wz) {
    size_t o = (size_t)blockIdx.x * blockDim.x + threadIdx.x;
    size_t j = o >> 10; int q = (int)(o & 1023);
    int g = q >> 2, kl = q & 3;
    int gate = (int)(j >> 11); size_t r = j & 2047;
    const float* W = (gate == 0) ? wi : (gate == 1) ? wf : (gate == 2) ? wo : wz;
    const float* src = W + r * (size_t)KDIM + g * 16 + 2 * kl;
    float2 v0 = *reinterpret_cast<const float2*>(src);
    float2 v1 = *reinterpret_cast<const float2*>(src + 8);
    reinterpret_cast<uint2*>(g_Wh)[o] = make_uint2(pack2(v0.x, v0.y), pack2(v1.x, v1.y));
}

// ---- fused GEMM (fp16 in, fp32 acc) + sLSTM epilogue ----
__global__ void __launch_bounds__(512, 1)
slstm_gemm(const __half* __restrict__ gA, const __half* __restrict__ gW,
           const float* __restrict__ c_in, const float* __restrict__ n_in,
           const float* __restrict__ m_in,
           const float* __restrict__ bi, const float* __restrict__ bf_,
           const float* __restrict__ bo, const float* __restrict__ bz,
           float* __restrict__ out)
{
    extern __shared__ char smc[];
    float* smf = reinterpret_cast<float*>(smc);
    const int tid = threadIdx.x;
    const int lane = tid & 31, wid = tid >> 5;
    const int wm = wid & 3, wn = wid >> 2;      // M-quarter, gate

    int bid = blockIdx.x;
    int sg = bid >> 9, r_ = bid & 511;
    int mt = (sg << 4) + (r_ & 15), dt = r_ >> 4;
    const int m0 = mt * MT, d0 = dt * DT;

    if (tid < 256) {
        int g = tid >> 6, jj = tid & 63;
        const float* bb = (g == 0) ? bi : (g == 1) ? bf_ : (g == 2) ? bo : bz;
        smf[BIAS_FO + tid] = bb[d0 + jj];
    }
    const uint32_t smb = smem_u32(smc);

    // cp.async assignments: A 1024 chunks (2/thr), B 2048 chunks (4/thr)
    const __half* aG[2]; uint32_t aS[2];
    #pragma unroll
    for (int q = 0; q < 2; ++q) {
        int id = tid + q * 512, row = id >> 3, c = id & 7;
        aS[q] = (uint32_t)(row * 128 + ((c ^ (2 * (row & 3))) << 4));
        aG[q] = gA + (size_t)(m0 + row) * KDIM + c * 8;
    }
    const __half* bG[4]; uint32_t bS[4];
    #pragma unroll
    for (int q = 0; q < 4; ++q) {
        int id = tid + q * 512, row = id >> 3, c = id & 7;
        int grow = ((row >> 6) << 11) + d0 + (row & 63);
        bS[q] = (uint32_t)(16384 + row * 128 + ((c ^ (2 * (row & 3))) << 4));
        bG[q] = gW + (size_t)grow * KDIM + c * 8;
    }

    float acc[2][8][4];
    #pragma unroll
    for (int i = 0; i < 2; ++i)
        #pragma unroll
        for (int j = 0; j < 8; ++j)
            #pragma unroll
            for (int t = 0; t < 4; ++t) acc[i][j][t] = 0.0f;

    #pragma unroll
    for (int p = 0; p < 2; ++p) {
        uint32_t base = smb + p * STG_B;
        #pragma unroll
        for (int q = 0; q < 2; ++q) { cpa16(base + aS[q], aG[q]); aG[q] += KCH; }
        #pragma unroll
        for (int q = 0; q < 4; ++q) { cpa16(base + bS[q], bG[q]); bG[q] += KCH; }
        asm volatile("cp.async.commit_group;" ::: "memory");
    }

    const int sub = lane >> 2;            // 0..7
    const int kl = lane & 3;
    const uint32_t klb = (uint32_t)((kl & 1) * 8);
    const int kh = kl >> 1;               // 0..1
    const int ar0 = wm * 32 + sub;
    const int bR0 = wn * 64 + sub;

    for (int ks = 0; ks < NKI; ++ks) {
        if (ks + 2 < NKI) asm volatile("cp.async.wait_group 1;" ::: "memory");
        else              asm volatile("cp.async.wait_group 0;" ::: "memory");
        __syncthreads();

        if (ks + 2 < NKI) {
            uint32_t base = smb + ((ks + 2) % 3) * STG_B;
            #pragma unroll
            for (int q = 0; q < 2; ++q) { cpa16(base + aS[q], aG[q]); aG[q] += KCH; }
            #pragma unroll
            for (int q = 0; q < 4; ++q) { cpa16(base + bS[q], bG[q]); bG[q] += KCH; }
            asm volatile("cp.async.commit_group;" ::: "memory");
        }

        const uint32_t As = smb + (ks % 3) * STG_B;
        const uint32_t Bs = As + 16384;
        #pragma unroll
        for (int g = 0; g < 4; ++g) {
            const uint32_t cidx = (uint32_t)((g << 1) | kh);
            uint32_t af[2][4];
            #pragma unroll
            for (int i = 0; i < 2; ++i) {
                int r1 = ar0 + i * 16;
                uint32_t a1 = As + r1 * 128 + ((cidx ^ (2 * (r1 & 3))) << 4) + klb;
                int r2 = r1 + 8;
                uint32_t a2 = As + r2 * 128 + ((cidx ^ (2 * (r2 & 3))) << 4) + klb;
                lds64(a1, af[i][0], af[i][2]);
                lds64(a2, af[i][1], af[i][3]);
            }
            #pragma unroll
            for (int j = 0; j < 8; ++j) {
                int rB = bR0 + j * 8;
                uint32_t ba = Bs + rB * 128 + ((cidx ^ (2 * (rB & 3))) << 4) + klb;
                uint32_t bf[2];
                lds64(ba, bf[0], bf[1]);
                mma_f16(acc[0][j], af[0], bf);
                mma_f16(acc[1][j], af[1], bf);
            }
        }
        __syncthreads();
    }

    // accums -> per-gate smem buffers (reuse pipeline smem)
    {
        float* sgb = smf + wn * EPI_GS;
        #pragma unroll
        for (int i = 0; i < 2; ++i) {
            int rr = wm * 32 + i * 16 + sub;
            #pragma unroll
            for (int j = 0; j < 8; ++j) {
                int cc = j * 8 + 2 * kl;
                *reinterpret_cast<float2*>(&sgb[rr * 66 + cc]) =
                    make_float2(acc[i][j][0], acc[i][j][1]);
                *reinterpret_cast<float2*>(&sgb[(rr + 8) * 66 + cc]) =
                    make_float2(acc[i][j][2], acc[i][j][3]);
            }
        }
    }
    __syncthreads();

    {
        const int dloc = tid & 63, mb = tid >> 6;   // mb 0..7
        const float bI = smf[BIAS_FO + dloc];
        const float bF = smf[BIAS_FO + 64 + dloc];
        const float bO = smf[BIAS_FO + 128 + dloc];
        const float bZ = smf[BIAS_FO + 192 + dloc];
        const size_t PL = (size_t)BATCH * DIMC;
        #pragma unroll 4
        for (int rr = 0; rr < 16; ++rr) {
            int mm = rr * 8 + mb;
            size_t gx = (size_t)(m0 + mm) * DIMC + d0 + dloc;
            float it = smf[0 * EPI_GS + mm * 66 + dloc] + bI;
            float ft = smf[1 * EPI_GS + mm * 66 + dloc] + bF;
            float ot = smf[2 * EPI_GS + mm * 66 + dloc] + bO;
            float zt = smf[3 * EPI_GS + mm * 66 + dloc] + bZ;
            float cv = c_in[gx], nv = n_in[gx], mv = m_in[gx];
            float z  = tanhf(zt);
            float mn = fmaxf(ft + mv, it);
            float ei = __expf(it - mn);
            float ef = __expf(ft + mv - mn);
            float cn = ef * cv + ei * z;
            float nn2 = ef * nv + ei;
            float sgm = 1.0f / (1.0f + __expf(-ot));
            float hn = sgm * cn / (nn2 + 1e-6f);
            out[gx]          = hn;
            out[PL + gx]     = cn;
            out[2 * PL + gx] = nn2;
            out[3 * PL + gx] = mn;
        }
    }
}

extern "C" void kernel_launch(void* const* d_in, const int* in_sizes, int n_in_cnt,
                              void* d_out, int out_size)
{
    (void)in_sizes; (void)n_in_cnt; (void)out_size;
    const float* x  = (const float*)d_in[0];
    const float* h  = (const float*)d_in[1];
    const float* c  = (const float*)d_in[2];
    const float* nn = (const float*)d_in[3];
    const float* m  = (const float*)d_in[4];
    const float* Wi = (const float*)d_in[5];
    const float* bi = (const float*)d_in[6];
    const float* Wf = (const float*)d_in[7];
    const float* bf = (const float*)d_in[8];
    const float* Wo = (const float*)d_in[9];
    const float* bo = (const float*)d_in[10];
    const float* Wz = (const float*)d_in[11];
    const float* bz = (const float*)d_in[12];
    float* out = (float*)d_out;

    void* pA = nullptr; void* pW = nullptr;
    cudaGetSymbolAddress(&pA, g_Ah);
    cudaGetSymbolAddress(&pW, g_Wh);

    // quads: BATCH*KDIM/4 = 8388608 ; same for W (8192*4096/4)
    prep_A_kernel<<<32768, 256>>>(x, h);
    prep_W_kernel<<<32768, 256>>>(Wi, Wf, Wo, Wz);

    cudaFuncSetAttribute(slstm_gemm, cudaFuncAttributeMaxDynamicSharedMemorySize, SMEM_B);
    int grid = (BATCH / MT) * (DIMC / DT);   // 2048
    slstm_gemm<<<grid, 512, SMEM_B>>>((const __half*)pA, (const __half*)pW,
                                      c, nn, m, bi, bf, bo, bz, out);
}

// round 5
// speedup vs baseline: 2.4723x; 1.0941x over previous
#include <cuda_runtime.h>
#include <cuda.h>
#include <cuda_fp16.h>
#include <cstdint>
#include <cstdio>

#define BATCH 8192
#define DIMC  2048
#define KDIM  4096

#define MT 128
#define DT 64              // d-cols per gate per CTA; N_total = 256
#define KCH 64             // k halves per stage (128B rows)
#define NKI (KDIM / KCH)   // 64
#define STG_B 49152        // A 128*128B + B 256*128B
#define EPI_GS 8448        // floats per gate buffer (128*66)
#define BIAS_FO 36864      // float offset of bias (= 3*STG_B/4)
#define SMEM_B 148480      // 3*STG_B + 1024

__device__ __half g_Ah[(size_t)BATCH * KDIM];
__device__ __half g_Wh[(size_t)4 * DIMC * KDIM];

__device__ __forceinline__ uint32_t smem_u32(const void* p) {
    uint32_t a;
    asm("{ .reg .u64 t; cvta.to.shared.u64 t, %1; cvt.u32.u64 %0, t; }" : "=r"(a) : "l"(p));
    return a;
}
__device__ __forceinline__ void cpa16(uint32_t s, const void* g) {
    asm volatile("cp.async.cg.shared.global [%0], [%1], 16;" :: "r"(s), "l"(g) : "memory");
}
#define LDM4(r, a) \
    asm volatile("ldmatrix.sync.aligned.m8n8.x4.shared.b16 {%0,%1,%2,%3}, [%4];" \
        : "=r"((r)[0]), "=r"((r)[1]), "=r"((r)[2]), "=r"((r)[3]) : "r"(a))
__device__ __forceinline__ void mma_f16(float* d, const uint32_t* a, const uint32_t* b) {
    asm volatile(
        "mma.sync.aligned.m16n8k16.row.col.f32.f16.f16.f32 "
        "{%0,%1,%2,%3}, {%4,%5,%6,%7}, {%8,%9}, {%0,%1,%2,%3};"
        : "+f"(d[0]), "+f"(d[1]), "+f"(d[2]), "+f"(d[3])
        : "r"(a[0]), "r"(a[1]), "r"(a[2]), "r"(a[3]), "r"(b[0]), "r"(b[1]));
}
__device__ __forceinline__ uint32_t pack2(float a, float b) {
    __half2 h = __floats2half2_rn(a, b);
    return *reinterpret_cast<uint32_t*>(&h);
}

// ---- prep: f32 -> f16 RNE, plain k-order, 8 floats/thread ----
__global__ void prep_A_kernel(const float* __restrict__ x, const float* __restrict__ h) {
    size_t idx = (size_t)blockIdx.x * blockDim.x + threadIdx.x;   // 16B-out id
    size_t row = idx >> 9; int seg = (int)(idx & 511);
    int cb = seg * 8;
    const float* src = (cb < 2048) ? (x + row * 2048 + cb) : (h + row * 2048 + (cb - 2048));
    float4 v0 = reinterpret_cast<const float4*>(src)[0];
    float4 v1 = reinterpret_cast<const float4*>(src)[1];
    reinterpret_cast<uint4*>(g_Ah)[idx] =
        make_uint4(pack2(v0.x, v0.y), pack2(v0.z, v0.w), pack2(v1.x, v1.y), pack2(v1.z, v1.w));
}
__global__ void prep_W_kernel(const float* __restrict__ wi, const float* __restrict__ wf,
                              const float* __restrict__ wo, const float* __restrict__ wz) {
    size_t idx = (size_t)blockIdx.x * blockDim.x + threadIdx.x;
    size_t j = idx >> 9; int seg = (int)(idx & 511);
    int gate = (int)(j >> 11); size_t r = j & 2047;
    const float* W = (gate == 0) ? wi : (gate == 1) ? wf : (gate == 2) ? wo : wz;
    const float* src = W + r * (size_t)KDIM + seg * 8;
    float4 v0 = reinterpret_cast<const float4*>(src)[0];
    float4 v1 = reinterpret_cast<const float4*>(src)[1];
    reinterpret_cast<uint4*>(g_Wh)[idx] =
        make_uint4(pack2(v0.x, v0.y), pack2(v0.z, v0.w), pack2(v1.x, v1.y), pack2(v1.z, v1.w));
}

// ---- fused GEMM (fp16 in, fp32 acc) + sLSTM ----
__global__ void __launch_bounds__(256, 1)
slstm_gemm(const __half* __restrict__ gA, const __half* __restrict__ gW,
           const float* __restrict__ c_in, const float* __restrict__ n_in,
           const float* __restrict__ m_in,
           const float* __restrict__ bi, const float* __restrict__ bf_,
           const float* __restrict__ bo, const float* __restrict__ bz,
           float* __restrict__ out)
{
    extern __shared__ char smc[];
    float* smf = reinterpret_cast<float*>(smc);
    const int tid = threadIdx.x;
    const int lane = tid & 31, wid = tid >> 5;
    const int wm = wid & 1, wn = wid >> 1;     // M-half, gate

    int bid = blockIdx.x;
    int sg = bid >> 9, r_ = bid & 511;
    int mt = (sg << 4) + (r_ & 15), dt = r_ >> 4;
    const int m0 = mt * MT, d0 = dt * DT;

    {
        int g = tid >> 6, jj = tid & 63;
        const float* bb = (g == 0) ? bi : (g == 1) ? bf_ : (g == 2) ? bo : bz;
        smf[BIAS_FO + tid] = bb[d0 + jj];
    }
    const uint32_t smb = smem_u32(smc);

    // cp.async offsets: A 1024 chunks (4/thr), B 2048 (8/thr)
    uint32_t aS[4], aO[4];
    #pragma unroll
    for (int q = 0; q < 4; ++q) {
        int id = tid + q * 256, row = id >> 3, c = id & 7;
        aS[q] = (uint32_t)(row * 128 + ((c ^ (row & 7)) << 4));
        aO[q] = (uint32_t)((m0 + row) * KDIM + c * 8);
    }
    uint32_t bS[8], bO[8];
    #pragma unroll
    for (int q = 0; q < 8; ++q) {
        int id = tid + q * 256, row = id >> 3, c = id & 7;
        int grow = ((row >> 6) << 11) + d0 + (row & 63);
        bS[q] = (uint32_t)(16384 + row * 128 + ((c ^ (row & 7)) << 4));
        bO[q] = (uint32_t)(grow * KDIM + c * 8);
    }

    // ldmatrix lane addressing
    const int l7 = lane & 7, l3 = (lane >> 3) & 1, l4 = (lane >> 4) & 1;
    uint32_t rpA[4], rmA[4], rpB[4], rmB[4];
    #pragma unroll
    for (int i = 0; i < 4; ++i) {
        int ra = wm * 64 + i * 16 + l3 * 8 + l7;
        rpA[i] = (uint32_t)(ra * 128); rmA[i] = (uint32_t)(ra & 7);
        int rb = wn * 64 + i * 16 + l4 * 8 + l7;
        rpB[i] = (uint32_t)(16384 + rb * 128); rmB[i] = (uint32_t)(rb & 7);
    }

    float acc[4][8][4];
    #pragma unroll
    for (int i = 0; i < 4; ++i)
        #pragma unroll
        for (int j = 0; j < 8; ++j)
            #pragma unroll
            for (int t = 0; t < 4; ++t) acc[i][j][t] = 0.0f;

    #pragma unroll
    for (int p = 0; p < 2; ++p) {
        uint32_t base = smb + p * STG_B;
        int ko = p * KCH;
        #pragma unroll
        for (int q = 0; q < 4; ++q) cpa16(base + aS[q], gA + aO[q] + ko);
        #pragma unroll
        for (int q = 0; q < 8; ++q) cpa16(base + bS[q], gW + bO[q] + ko);
        asm volatile("cp.async.commit_group;" ::: "memory");
    }

    for (int ks = 0; ks < NKI; ++ks) {
        if (ks + 2 < NKI) asm volatile("cp.async.wait_group 1;" ::: "memory");
        else              asm volatile("cp.async.wait_group 0;" ::: "memory");
        __syncthreads();

        if (ks + 2 < NKI) {
            uint32_t base = smb + ((ks + 2) % 3) * STG_B;
            int ko = (ks + 2) * KCH;
            #pragma unroll
            for (int q = 0; q < 4; ++q) cpa16(base + aS[q], gA + aO[q] + ko);
            #pragma unroll
            for (int q = 0; q < 8; ++q) cpa16(base + bS[q], gW + bO[q] + ko);
            asm volatile("cp.async.commit_group;" ::: "memory");
        }

        const uint32_t St = smb + (ks % 3) * STG_B;
        #pragma unroll
        for (int s = 0; s < 4; ++s) {
            uint32_t aF[4][4], bF[4][4];
            const uint32_t cA = (uint32_t)(2 * s + l4);
            const uint32_t cB = (uint32_t)(2 * s + l3);
            #pragma unroll
            for (int i = 0; i < 4; ++i)
                LDM4(aF[i], St + rpA[i] + (((cA ^ rmA[i])) << 4));
            #pragma unroll
            for (int j2 = 0; j2 < 4; ++j2)
                LDM4(bF[j2], St + rpB[j2] + (((cB ^ rmB[j2])) << 4));
            #pragma unroll
            for (int i = 0; i < 4; ++i)
                #pragma unroll
                for (int j2 = 0; j2 < 4; ++j2) {
                    mma_f16(acc[i][2 * j2],     aF[i], &bF[j2][0]);
                    mma_f16(acc[i][2 * j2 + 1], aF[i], &bF[j2][2]);
                }
        }
    }
    __syncthreads();

    // accums -> per-gate smem
    {
        const int sub = lane >> 2, kl = lane & 3;
        float* sgb = smf + wn * EPI_GS;
        #pragma unroll
        for (int i = 0; i < 4; ++i) {
            int rr = wm * 64 + i * 16 + sub;
            #pragma unroll
            for (int j = 0; j < 8; ++j) {
                int cc = j * 8 + 2 * kl;
                *reinterpret_cast<float2*>(&sgb[rr * 66 + cc]) =
                    make_float2(acc[i][j][0], acc[i][j][1]);
                *reinterpret_cast<float2*>(&sgb[(rr + 8) * 66 + cc]) =
                    make_float2(acc[i][j][2], acc[i][j][3]);
            }
        }
    }
    __syncthreads();

    {
        const int dloc = tid & 63, mb = tid >> 6;   // mb 0..3
        const float bI = smf[BIAS_FO + dloc];
        const float bF = smf[BIAS_FO + 64 + dloc];
        const float bO = smf[BIAS_FO + 128 + dloc];
        const float bZ = smf[BIAS_FO + 192 + dloc];
        const size_t PL = (size_t)BATCH * DIMC;
        #pragma unroll 4
        for (int rr = 0; rr < 32; ++rr) {
            int mm = rr * 4 + mb;
            size_t gx = (size_t)(m0 + mm) * DIMC + d0 + dloc;
            float it = smf[0 * EPI_GS + mm * 66 + dloc] + bI;
            float ft = smf[1 * EPI_GS + mm * 66 + dloc] + bF;
            float ot = smf[2 * EPI_GS + mm * 66 + dloc] + bO;
            float zt = smf[3 * EPI_GS + mm * 66 + dloc] + bZ;
            float cv = c_in[gx], nv = n_in[gx], mv = m_in[gx];
            float z  = tanhf(zt);
            float mn = fmaxf(ft + mv, it);
            float ei = __expf(it - mn);
            float ef = __expf(ft + mv - mn);
            float cn = ef * cv + ei * z;
            float nn2 = ef * nv + ei;
            float sgm = 1.0f / (1.0f + __expf(-ot));
            float hn = sgm * cn / (nn2 + 1e-6f);
            out[gx]          = hn;
            out[PL + gx]     = cn;
            out[2 * PL + gx] = nn2;
            out[3 * PL + gx] = mn;
        }
    }
}

extern "C" void kernel_launch(void* const* d_in, const int* in_sizes, int n_in_cnt,
                              void* d_out, int out_size)
{
    (void)in_sizes; (void)n_in_cnt; (void)out_size;
    const float* x  = (const float*)d_in[0];
    const float* h  = (const float*)d_in[1];
    const float* c  = (const float*)d_in[2];
    const float* nn = (const float*)d_in[3];
    const float* m  = (const float*)d_in[4];
    const float* Wi = (const float*)d_in[5];
    const float* bi = (const float*)d_in[6];
    const float* Wf = (const float*)d_in[7];
    const float* bf = (const float*)d_in[8];
    const float* Wo = (const float*)d_in[9];
    const float* bo = (const float*)d_in[10];
    const float* Wz = (const float*)d_in[11];
    const float* bz = (const float*)d_in[12];
    float* out = (float*)d_out;

    void* pA = nullptr; void* pW = nullptr;
    cudaGetSymbolAddress(&pA, g_Ah);
    cudaGetSymbolAddress(&pW, g_Wh);

    prep_A_kernel<<<16384, 256>>>(x, h);
    prep_W_kernel<<<16384, 256>>>(Wi, Wf, Wo, Wz);

    cudaFuncSetAttribute(slstm_gemm, cudaFuncAttributeMaxDynamicSharedMemorySize, SMEM_B);
    int grid = (BATCH / MT) * (DIMC / DT);   // 2048
    slstm_gemm<<<grid, 256, SMEM_B>>>((const __half*)pA, (const __half*)pW,
                                      c, nn, m, bi, bf, bo, bz, out);
}

// round 6
// speedup vs baseline: 3.1655x; 1.2804x over previous
#include <cuda_runtime.h>
#include <cuda.h>
#include <cuda_fp16.h>
#include <cstdint>
#include <cstdio>

#define BATCH 8192
#define DIMC  2048
#define KDIM  4096

#define MT 128
#define DT 32              // d-cols per gate per CTA; N_total = 128
#define KCH 64             // k halves per stage (128B rows)
#define NKI (KDIM / KCH)   // 64
#define STG_B 32768        // A 128*128B + B 128*128B
#define EPI_GS 4352        // floats per gate buffer (128*34)
#define BIAS_FO 24576      // float offset of bias (= 3*STG_B/4)
#define SMEM_B 98816       // 3*STG_B + 512

__device__ __half g_Ah[(size_t)BATCH * KDIM];
__device__ __half g_Wh[(size_t)4 * DIMC * KDIM];

__device__ __forceinline__ uint32_t smem_u32(const void* p) {
    uint32_t a;
    asm("{ .reg .u64 t; cvta.to.shared.u64 t, %1; cvt.u32.u64 %0, t; }" : "=r"(a) : "l"(p));
    return a;
}
__device__ __forceinline__ void cpa16(uint32_t s, const void* g) {
    asm volatile("cp.async.cg.shared.global [%0], [%1], 16;" :: "r"(s), "l"(g) : "memory");
}
#define LDM4(r, a) \
    asm volatile("ldmatrix.sync.aligned.m8n8.x4.shared.b16 {%0,%1,%2,%3}, [%4];" \
        : "=r"((r)[0]), "=r"((r)[1]), "=r"((r)[2]), "=r"((r)[3]) : "r"(a))
__device__ __forceinline__ void mma_f16(float* d, const uint32_t* a, const uint32_t* b) {
    asm volatile(
        "mma.sync.aligned.m16n8k16.row.col.f32.f16.f16.f32 "
        "{%0,%1,%2,%3}, {%4,%5,%6,%7}, {%8,%9}, {%0,%1,%2,%3};"
        : "+f"(d[0]), "+f"(d[1]), "+f"(d[2]), "+f"(d[3])
        : "r"(a[0]), "r"(a[1]), "r"(a[2]), "r"(a[3]), "r"(b[0]), "r"(b[1]));
}
__device__ __forceinline__ uint32_t pack2(float a, float b) {
    __half2 h = __floats2half2_rn(a, b);
    return *reinterpret_cast<uint32_t*>(&h);
}

// ---- prep: f32 -> f16 RNE, plain k-order ----
__global__ void prep_A_kernel(const float* __restrict__ x, const float* __restrict__ h) {
    size_t idx = (size_t)blockIdx.x * blockDim.x + threadIdx.x;
    size_t row = idx >> 9; int seg = (int)(idx & 511);
    int cb = seg * 8;
    const float* src = (cb < 2048) ? (x + row * 2048 + cb) : (h + row * 2048 + (cb - 2048));
    float4 v0 = reinterpret_cast<const float4*>(src)[0];
    float4 v1 = reinterpret_cast<const float4*>(src)[1];
    reinterpret_cast<uint4*>(g_Ah)[idx] =
        make_uint4(pack2(v0.x, v0.y), pack2(v0.z, v0.w), pack2(v1.x, v1.y), pack2(v1.z, v1.w));
}
__global__ void prep_W_kernel(const float* __restrict__ wi, const float* __restrict__ wf,
                              const float* __restrict__ wo, const float* __restrict__ wz) {
    size_t idx = (size_t)blockIdx.x * blockDim.x + threadIdx.x;
    size_t j = idx >> 9; int seg = (int)(idx & 511);
    int gate = (int)(j >> 11); size_t r = j & 2047;
    const float* W = (gate == 0) ? wi : (gate == 1) ? wf : (gate == 2) ? wo : wz;
    const float* src = W + r * (size_t)KDIM + seg * 8;
    float4 v0 = reinterpret_cast<const float4*>(src)[0];
    float4 v1 = reinterpret_cast<const float4*>(src)[1];
    reinterpret_cast<uint4*>(g_Wh)[idx] =
        make_uint4(pack2(v0.x, v0.y), pack2(v0.z, v0.w), pack2(v1.x, v1.y), pack2(v1.z, v1.w));
}

// ---- fused GEMM (fp16 in, fp32 acc) + sLSTM ----
__global__ void __launch_bounds__(256, 2)
slstm_gemm(const __half* __restrict__ gA, const __half* __restrict__ gW,
           const float* __restrict__ c_in, const float* __restrict__ n_in,
           const float* __restrict__ m_in,
           const float* __restrict__ bi, const float* __restrict__ bf_,
           const float* __restrict__ bo, const float* __restrict__ bz,
           float* __restrict__ out)
{
    extern __shared__ char smc[];
    float* smf = reinterpret_cast<float*>(smc);
    const int tid = threadIdx.x;
    const int lane = tid & 31, wid = tid >> 5;
    const int wm = wid & 1, wn = wid >> 1;     // M-half, gate

    int bid = blockIdx.x;
    int sg = bid >> 10, r_ = bid & 1023;
    int mt = (sg << 4) + (r_ & 15), dt = r_ >> 4;   // 16 m x 64 d per supergroup
    const int m0 = mt * MT, d0 = dt * DT;

    if (tid < 128) {
        int g = tid >> 5, jj = tid & 31;
        const float* bb = (g == 0) ? bi : (g == 1) ? bf_ : (g == 2) ? bo : bz;
        smf[BIAS_FO + tid] = bb[d0 + jj];
    }
    const uint32_t smb = smem_u32(smc);

    // cp.async: A 1024 chunks (4/thr), B 1024 chunks (4/thr)
    uint32_t aS[4], aO[4], bS[4], bO[4];
    #pragma unroll
    for (int q = 0; q < 4; ++q) {
        int id = tid + q * 256, row = id >> 3, c = id & 7;
        aS[q] = (uint32_t)(row * 128 + ((c ^ (row & 7)) << 4));
        aO[q] = (uint32_t)((m0 + row) * KDIM + c * 8);
        int grow = ((row >> 5) << 11) + d0 + (row & 31);
        bS[q] = (uint32_t)(16384 + row * 128 + ((c ^ (row & 7)) << 4));
        bO[q] = (uint32_t)(grow * KDIM + c * 8);
    }

    // ldmatrix bases: addr = (St + bas) ^ (c<<4); swizzle XOR confined to bits [4:7)
    const int l7 = lane & 7, l3 = (lane >> 3) & 1, l4 = (lane >> 4) & 1;
    uint32_t basA[4], basB[2];
    #pragma unroll
    for (int i = 0; i < 4; ++i) {
        int ra = wm * 64 + i * 16 + l3 * 8 + l7;
        basA[i] = (uint32_t)(ra * 128 + ((ra & 7) << 4));
    }
    #pragma unroll
    for (int j2 = 0; j2 < 2; ++j2) {
        int rb = wn * 32 + j2 * 16 + l4 * 8 + l7;
        basB[j2] = (uint32_t)(16384 + rb * 128 + ((rb & 7) << 4));
    }

    float acc[4][4][4];
    #pragma unroll
    for (int i = 0; i < 4; ++i)
        #pragma unroll
        for (int j = 0; j < 4; ++j)
            #pragma unroll
            for (int t = 0; t < 4; ++t) acc[i][j][t] = 0.0f;

    #pragma unroll
    for (int p = 0; p < 2; ++p) {
        uint32_t base = smb + p * STG_B;
        int ko = p * KCH;
        #pragma unroll
        for (int q = 0; q < 4; ++q) { cpa16(base + aS[q], gA + aO[q] + ko);
                                      cpa16(base + bS[q], gW + bO[q] + ko); }
        asm volatile("cp.async.commit_group;" ::: "memory");
    }

    for (int ks = 0; ks < NKI; ++ks) {
        if (ks + 2 < NKI) asm volatile("cp.async.wait_group 1;" ::: "memory");
        else              asm volatile("cp.async.wait_group 0;" ::: "memory");
        __syncthreads();

        if (ks + 2 < NKI) {
            uint32_t base = smb + ((ks + 2) % 3) * STG_B;
            int ko = (ks + 2) * KCH;
            #pragma unroll
            for (int q = 0; q < 4; ++q) { cpa16(base + aS[q], gA + aO[q] + ko);
                                          cpa16(base + bS[q], gW + bO[q] + ko); }
            asm volatile("cp.async.commit_group;" ::: "memory");
        }

        const uint32_t St = smb + (ks % 3) * STG_B;
        #pragma unroll
        for (int s = 0; s < 4; ++s) {
            uint32_t aF[4][4], bF[2][4];
            const uint32_t xA = (uint32_t)((2 * s + l4) << 4);
            const uint32_t xB = (uint32_t)((2 * s + l3) << 4);
            #pragma unroll
            for (int j2 = 0; j2 < 2; ++j2)
                LDM4(bF[j2], (St + basB[j2]) ^ xB);
            #pragma unroll
            for (int i = 0; i < 4; ++i)
                LDM4(aF[i], (St + basA[i]) ^ xA);
            #pragma unroll
            for (int i = 0; i < 4; ++i)
                #pragma unroll
                for (int j2 = 0; j2 < 2; ++j2) {
                    mma_f16(acc[i][2 * j2],     aF[i], &bF[j2][0]);
                    mma_f16(acc[i][2 * j2 + 1], aF[i], &bF[j2][2]);
                }
        }
    }
    __syncthreads();

    // accums -> per-gate smem
    {
        const int sub = lane >> 2, kl = lane & 3;
        float* sgb = smf + wn * EPI_GS;
        #pragma unroll
        for (int i = 0; i < 4; ++i) {
            int rr = wm * 64 + i * 16 + sub;
            #pragma unroll
            for (int j = 0; j < 4; ++j) {
                int cc = j * 8 + 2 * kl;
                *reinterpret_cast<float2*>(&sgb[rr * 34 + cc]) =
                    make_float2(acc[i][j][0], acc[i][j][1]);
                *reinterpret_cast<float2*>(&sgb[(rr + 8) * 34 + cc]) =
                    make_float2(acc[i][j][2], acc[i][j][3]);
            }
        }
    }
    __syncthreads();

    {
        const int dloc = tid & 31, mb = tid >> 5;   // mb 0..7
        const float bI = smf[BIAS_FO + dloc];
        const float bF = smf[BIAS_FO + 32 + dloc];
        const float bO = smf[BIAS_FO + 64 + dloc];
        const float bZ = smf[BIAS_FO + 96 + dloc];
        const size_t PL = (size_t)BATCH * DIMC;
        #pragma unroll 4
        for (int rr = 0; rr < 16; ++rr) {
            int mm = rr * 8 + mb;
            size_t gx = (size_t)(m0 + mm) * DIMC + d0 + dloc;
            float it = smf[0 * EPI_GS + mm * 34 + dloc] + bI;
            float ft = smf[1 * EPI_GS + mm * 34 + dloc] + bF;
            float ot = smf[2 * EPI_GS + mm * 34 + dloc] + bO;
            float zt = smf[3 * EPI_GS + mm * 34 + dloc] + bZ;
            float cv = c_in[gx], nv = n_in[gx], mv = m_in[gx];
            float z  = tanhf(zt);
            float mn = fmaxf(ft + mv, it);
            float ei = __expf(it - mn);
            float ef = __expf(ft + mv - mn);
            float cn = ef * cv + ei * z;
            float nn2 = ef * nv + ei;
            float sgm = 1.0f / (1.0f + __expf(-ot));
            float hn = sgm * cn / (nn2 + 1e-6f);
            out[gx]          = hn;
            out[PL + gx]     = cn;
            out[2 * PL + gx] = nn2;
            out[3 * PL + gx] = mn;
        }
    }
}

extern "C" void kernel_launch(void* const* d_in, const int* in_sizes, int n_in_cnt,
                              void* d_out, int out_size)
{
    (void)in_sizes; (void)n_in_cnt; (void)out_size;
    const float* x  = (const float*)d_in[0];
    const float* h  = (const float*)d_in[1];
    const float* c  = (const float*)d_in[2];
    const float* nn = (const float*)d_in[3];
    const float* m  = (const float*)d_in[4];
    const float* Wi = (const float*)d_in[5];
    const float* bi = (const float*)d_in[6];
    const float* Wf = (const float*)d_in[7];
    const float* bf = (const float*)d_in[8];
    const float* Wo = (const float*)d_in[9];
    const float* bo = (const float*)d_in[10];
    const float* Wz = (const float*)d_in[11];
    const float* bz = (const float*)d_in[12];
    float* out = (float*)d_out;

    void* pA = nullptr; void* pW = nullptr;
    cudaGetSymbolAddress(&pA, g_Ah);
    cudaGetSymbolAddress(&pW, g_Wh);

    prep_A_kernel<<<16384, 256>>>(x, h);
    prep_W_kernel<<<16384, 256>>>(Wi, Wf, Wo, Wz);

    cudaFuncSetAttribute(slstm_gemm, cudaFuncAttributeMaxDynamicSharedMemorySize, SMEM_B);
    int grid = (BATCH / MT) * (DIMC / DT);   // 64 * 64 = 4096
    slstm_gemm<<<grid, 256, SMEM_B>>>((const __half*)pA, (const __half*)pW,
                                      c, nn, m, bi, bf, bo, bz, out);
}